// round 12
// baseline (speedup 1.0000x reference)
#include <cuda_runtime.h>
#include <cuda_bf16.h>
#include <stdint.h>

// GCN 2-layer, N=50000, E=640000, 128 -> 128(relu) -> 40.
// y = dinv*(x@W) via bf16x3 tensor-core GEMM; agg via CSR warp-gather; out = dinv*agg + b.

#define NN 50000
#define NE 640000

// ---- scratch (device globals; allocation forbidden) ----
__device__ int   g_is32;
__device__ int   g_eidx[NE];
__device__ int   g_rowptr[NN + 1];
__device__ int   g_cursor[NN];
__device__ int   g_rowtmp[NN];
__device__ int   g_bsum[256];
__device__ int   g_boff[256];
__device__ int   g_deg[NN];
__device__ float g_dinv[NN];
__device__ __align__(16) float g_y1[NN * 128];
__device__ __align__(16) float g_h [NN * 128];
__device__ __align__(16) float g_y2[NN * 40];
__device__ __align__(4) __nv_bfloat16 g_W1h[128 * 128], g_W1l[128 * 128];
__device__ __align__(4) __nv_bfloat16 g_W2h[128 * 40],  g_W2l[128 * 40];

// ---------------- prologue ----------------
__global__ void k_probe(const int* __restrict__ ei32) {
    int i = threadIdx.x;                      // odd 32-bit words 1..511
    if (i == 0) g_is32 = 0;
    __syncthreads();
    if (ei32[2 * i + 1] != 0) g_is32 = 1;     // int64 high halves all 0
}

__global__ void k_zero_deg(int nn) {
    int i = blockIdx.x * blockDim.x + threadIdx.x;
    if (i < nn) g_deg[i] = 0;
}

__global__ void k_count(const int* __restrict__ ei32, int ne, int nn) {
    int e = blockIdx.x * blockDim.x + threadIdx.x;
    if (e >= ne) return;
    int d = g_is32 ? ei32[ne + e] : ei32[2 * ne + 2 * e];
    d = ((unsigned)d < (unsigned)nn) ? d : 0;
    atomicAdd(&g_deg[d], 1);
}

__global__ void k_scan1(int nn) {
    __shared__ int s[256];
    int t = threadIdx.x;
    int i = blockIdx.x * 256 + t;
    int v = (i < nn) ? g_deg[i] : 0;
    s[t] = v;
    __syncthreads();
    for (int off = 1; off < 256; off <<= 1) {
        int add = (t >= off) ? s[t - off] : 0;
        __syncthreads();
        s[t] += add;
        __syncthreads();
    }
    if (i < nn) g_rowtmp[i] = s[t] - v;
    if (t == 255) g_bsum[blockIdx.x] = s[255];
}

__global__ void k_scan2(int nb) {
    __shared__ int s[256];
    int t = threadIdx.x;
    int v = (t < nb) ? g_bsum[t] : 0;
    s[t] = v;
    __syncthreads();
    for (int off = 1; off < 256; off <<= 1) {
        int add = (t >= off) ? s[t - off] : 0;
        __syncthreads();
        s[t] += add;
        __syncthreads();
    }
    g_boff[t] = s[t] - v;
}

__global__ void k_scan3(int nn, int ne) {
    int i = blockIdx.x * blockDim.x + threadIdx.x;
    if (i < nn) {
        int rp = g_rowtmp[i] + g_boff[i >> 8];
        g_rowptr[i] = rp;
        g_cursor[i] = rp;
        g_dinv[i] = rsqrtf((float)(g_deg[i] + 1));
    }
    if (i == 0) g_rowptr[nn] = ne;
}

__global__ void k_fill(const int* __restrict__ ei32, int ne, int nn) {
    int e = blockIdx.x * blockDim.x + threadIdx.x;
    if (e >= ne) return;
    int s, d;
    if (g_is32) { s = ei32[e];     d = ei32[ne + e]; }
    else        { s = ei32[2 * e]; d = ei32[2 * ne + 2 * e]; }
    s = ((unsigned)s < (unsigned)nn) ? s : 0;
    d = ((unsigned)d < (unsigned)nn) ? d : 0;
    int pos = atomicAdd(&g_cursor[d], 1);
    g_eidx[pos] = s;
}

// ---------------- weight split: W -> bf16 hi + bf16 lo ----------------
__global__ void k_splitW(const float* __restrict__ W1, const float* __restrict__ W2) {
    int i = blockIdx.x * blockDim.x + threadIdx.x;
    if (i < 128 * 128) {
        float v = W1[i];
        __nv_bfloat16 h = __float2bfloat16(v);
        g_W1h[i] = h;
        g_W1l[i] = __float2bfloat16(v - __bfloat162float(h));
    } else if (i < 128 * 128 + 128 * 40) {
        int j = i - 128 * 128;
        float v = W2[j];
        __nv_bfloat16 h = __float2bfloat16(v);
        g_W2h[j] = h;
        g_W2l[j] = __float2bfloat16(v - __bfloat162float(h));
    }
}

// ---------------- tensor-core GEMM (bf16x3) ----------------
__device__ __forceinline__ uint32_t s2u(const void* p) {
    return (uint32_t)__cvta_generic_to_shared(p);
}
__device__ __forceinline__ uint32_t pack2(float a, float b) {
    __nv_bfloat162 t = __floats2bfloat162_rn(a, b);
    return *(uint32_t*)&t;
}
__device__ __forceinline__ void ldsm_x4(uint32_t a[4], uint32_t addr) {
    asm volatile("ldmatrix.sync.aligned.m8n8.x4.shared.b16 {%0,%1,%2,%3},[%4];"
                 : "=r"(a[0]), "=r"(a[1]), "=r"(a[2]), "=r"(a[3]) : "r"(addr));
}
__device__ __forceinline__ void ldsm_x2t(uint32_t b[2], uint32_t addr) {
    asm volatile("ldmatrix.sync.aligned.m8n8.x2.trans.shared.b16 {%0,%1},[%2];"
                 : "=r"(b[0]), "=r"(b[1]) : "r"(addr));
}
__device__ __forceinline__ void mma16816(float d[4], const uint32_t a[4], const uint32_t b[2]) {
    asm volatile("mma.sync.aligned.m16n8k16.row.col.f32.bf16.bf16.f32 "
                 "{%0,%1,%2,%3},{%4,%5,%6,%7},{%8,%9},{%0,%1,%2,%3};"
                 : "+f"(d[0]), "+f"(d[1]), "+f"(d[2]), "+f"(d[3])
                 : "r"(a[0]), "r"(a[1]), "r"(a[2]), "r"(a[3]), "r"(b[0]), "r"(b[1]));
}

// LAYER 1: in = x (arg), W = g_W1h/l, out = g_y1, NW=128
// LAYER 2: in = g_h,     W = g_W2h/l, out = g_y2, NW=40
// Block: 256 threads (8 warps x m16), M-tile 128, full N.
template <int LAYER>
__global__ void k_gemm_tc(const float* __restrict__ xin, int nn) {
    constexpr int NW = (LAYER == 1) ? 128 : 40;
    constexpr int NT = NW / 8;                  // n-tiles
    constexpr int XP = 136;                     // padded x width (bf16)
    constexpr int WP = (LAYER == 1) ? 136 : 56; // padded w width (bank-safe)

    extern __shared__ __nv_bfloat16 sm[];
    __nv_bfloat16* xh = sm;
    __nv_bfloat16* xl = xh + 128 * XP;
    __nv_bfloat16* wh = xl + 128 * XP;
    __nv_bfloat16* wl = wh + 128 * WP;

    const float* in = (LAYER == 1) ? xin : (const float*)g_h;
    float* outp     = (LAYER == 1) ? g_y1 : g_y2;
    const __nv_bfloat16* Wh = (LAYER == 1) ? g_W1h : g_W2h;
    const __nv_bfloat16* Wl = (LAYER == 1) ? g_W1l : g_W2l;

    int tid = threadIdx.x;
    int m_base = blockIdx.x * 128;

    // load W (bf16 pre-split) into padded smem, pairwise
    const uint32_t* wsh = (const uint32_t*)Wh;
    const uint32_t* wsl = (const uint32_t*)Wl;
    for (int i = tid; i < 128 * NW / 2; i += 256) {
        int r = (2 * i) / NW, c = (2 * i) % NW;
        *(uint32_t*)&wh[r * WP + c] = wsh[i];
        *(uint32_t*)&wl[r * WP + c] = wsl[i];
    }
    // load + split x tile (128 x 128 fp32)
    for (int i = tid; i < 128 * 32; i += 256) {
        int r = i >> 5, cq = i & 31;
        int row = m_base + r;
        float4 v = make_float4(0.f, 0.f, 0.f, 0.f);
        if (row < nn) v = ((const float4*)(in + (size_t)row * 128))[cq];
        float hx = __bfloat162float(__float2bfloat16(v.x));
        float hy = __bfloat162float(__float2bfloat16(v.y));
        float hz = __bfloat162float(__float2bfloat16(v.z));
        float hw = __bfloat162float(__float2bfloat16(v.w));
        uint2 ph = make_uint2(pack2(v.x, v.y), pack2(v.z, v.w));
        uint2 pl = make_uint2(pack2(v.x - hx, v.y - hy), pack2(v.z - hz, v.w - hw));
        *(uint2*)&xh[r * XP + cq * 4] = ph;
        *(uint2*)&xl[r * XP + cq * 4] = pl;
    }
    __syncthreads();

    int warp = tid >> 5, lane = tid & 31;
    int mrow = warp * 16;

    float d[NT][4];
#pragma unroll
    for (int t = 0; t < NT; t++) { d[t][0] = d[t][1] = d[t][2] = d[t][3] = 0.f; }

    uint32_t xh_b = s2u(xh), xl_b = s2u(xl), wh_b = s2u(wh), wl_b = s2u(wl);
    uint32_t a_off = ((mrow + (lane & 15)) * XP + (lane >> 4) * 8) * 2;   // bytes
    uint32_t b_lrow = (lane & 15);

#pragma unroll
    for (int ks = 0; ks < 8; ks++) {
        uint32_t ah[4], al[4];
        ldsm_x4(ah, xh_b + a_off + ks * 32);
        ldsm_x4(al, xl_b + a_off + ks * 32);
        uint32_t brow = ((ks * 16 + b_lrow) * WP) * 2;
#pragma unroll
        for (int nt = 0; nt < NT; nt++) {
            uint32_t bh[2], bl[2];
            ldsm_x2t(bh, wh_b + brow + nt * 16);
            ldsm_x2t(bl, wl_b + brow + nt * 16);
            mma16816(d[nt], ah, bh);
            mma16816(d[nt], ah, bl);
            mma16816(d[nt], al, bh);
        }
    }

    int r0 = m_base + mrow + (lane >> 2);
    int r1 = r0 + 8;
    int c0 = (lane & 3) * 2;
    float di0 = (r0 < nn) ? g_dinv[r0] : 0.f;
    float di1 = (r1 < nn) ? g_dinv[r1] : 0.f;
#pragma unroll
    for (int nt = 0; nt < NT; nt++) {
        int col = nt * 8 + c0;
        if (r0 < nn) *(float2*)&outp[(size_t)r0 * NW + col] = make_float2(d[nt][0] * di0, d[nt][1] * di0);
        if (r1 < nn) *(float2*)&outp[(size_t)r1 * NW + col] = make_float2(d[nt][2] * di1, d[nt][3] * di1);
    }
}

// ---------------- layer 1 gather: h = relu(dinv*(y1[n] + sum y1[src]) + b1) ----------------
__global__ void k_gather1(const float* __restrict__ b1, int nn) {
    int warp = (blockIdx.x * blockDim.x + threadIdx.x) >> 5;
    if (warp >= nn) return;
    int q = threadIdx.x & 31;
    int n = warp;
    int beg = g_rowptr[n], end = g_rowptr[n + 1];
    float4 acc = ((const float4*)(g_y1 + (size_t)n * 128))[q];   // self loop
    int k = beg;
    for (; k + 3 < end; k += 4) {                                // 4 loads in flight
        int s0 = g_eidx[k], s1 = g_eidx[k + 1], s2 = g_eidx[k + 2], s3 = g_eidx[k + 3];
        float4 v0 = ((const float4*)(g_y1 + (size_t)s0 * 128))[q];
        float4 v1 = ((const float4*)(g_y1 + (size_t)s1 * 128))[q];
        float4 v2 = ((const float4*)(g_y1 + (size_t)s2 * 128))[q];
        float4 v3 = ((const float4*)(g_y1 + (size_t)s3 * 128))[q];
        acc.x += v0.x + v1.x + v2.x + v3.x;
        acc.y += v0.y + v1.y + v2.y + v3.y;
        acc.z += v0.z + v1.z + v2.z + v3.z;
        acc.w += v0.w + v1.w + v2.w + v3.w;
    }
    for (; k < end; k++) {
        int s = g_eidx[k];
        float4 v = ((const float4*)(g_y1 + (size_t)s * 128))[q];
        acc.x += v.x; acc.y += v.y; acc.z += v.z; acc.w += v.w;
    }
    float di = g_dinv[n];
    float4 b = ((const float4*)b1)[q];
    float4 h;
    h.x = fmaxf(fmaf(di, acc.x, b.x), 0.f);
    h.y = fmaxf(fmaf(di, acc.y, b.y), 0.f);
    h.z = fmaxf(fmaf(di, acc.z, b.z), 0.f);
    h.w = fmaxf(fmaf(di, acc.w, b.w), 0.f);
    ((float4*)(g_h + (size_t)n * 128))[q] = h;
}

// ---------------- layer 2 gather: out = dinv*(y2[n] + sum y2[src]) + b2 ----------------
__global__ void k_gather2(float* __restrict__ out, const float* __restrict__ b2, int nn) {
    int warp = (blockIdx.x * blockDim.x + threadIdx.x) >> 5;
    if (warp >= nn) return;
    int lane = threadIdx.x & 31;
    int n = warp;
    int beg = g_rowptr[n], end = g_rowptr[n + 1];
    int sub = lane / 10;                 // 0,1,2 active
    int q = lane % 10;
    float4 acc = make_float4(0.f, 0.f, 0.f, 0.f);
    if (sub == 0) acc = ((const float4*)(g_y2 + (size_t)n * 40))[q];   // self loop
    int k = (sub < 3) ? (beg + sub) : end;
    for (; k + 3 < end; k += 6) {        // 2 edges in flight per subgroup
        int s0 = g_eidx[k], s1 = g_eidx[k + 3];
        float4 v0 = *(const float4*)(g_y2 + (size_t)s0 * 40 + q * 4);
        float4 v1 = *(const float4*)(g_y2 + (size_t)s1 * 40 + q * 4);
        acc.x += v0.x + v1.x; acc.y += v0.y + v1.y;
        acc.z += v0.z + v1.z; acc.w += v0.w + v1.w;
    }
    if (k < end) {
        int s = g_eidx[k];
        float4 v = *(const float4*)(g_y2 + (size_t)s * 40 + q * 4);
        acc.x += v.x; acc.y += v.y; acc.z += v.z; acc.w += v.w;
    }
    unsigned m = 0xFFFFFFFFu;
    float ax = acc.x + __shfl_sync(m, acc.x, lane + 10) + __shfl_sync(m, acc.x, lane + 20);
    float ay = acc.y + __shfl_sync(m, acc.y, lane + 10) + __shfl_sync(m, acc.y, lane + 20);
    float az = acc.z + __shfl_sync(m, acc.z, lane + 10) + __shfl_sync(m, acc.z, lane + 20);
    float aw = acc.w + __shfl_sync(m, acc.w, lane + 10) + __shfl_sync(m, acc.w, lane + 20);
    if (lane < 10) {
        float di = g_dinv[n];
        float4 b = ((const float4*)b2)[q];
        float4 r;
        r.x = fmaf(di, ax, b.x);
        r.y = fmaf(di, ay, b.y);
        r.z = fmaf(di, az, b.z);
        r.w = fmaf(di, aw, b.w);
        ((float4*)(out + (size_t)n * 40))[q] = r;
    }
}

extern "C" void kernel_launch(void* const* d_in, const int* in_sizes, int n_in,
                              void* d_out, int out_size) {
    const float* x    = (const float*)d_in[0];
    const int*   ei32 = (const int*)d_in[1];
    const float* W1   = (const float*)d_in[2];
    const float* b1   = (const float*)d_in[3];
    const float* W2   = (const float*)d_in[4];
    const float* b2   = (const float*)d_in[5];
    float*       out  = (float*)d_out;

    const int nn = in_sizes[0] / 128;     // 50000
    const int ne = in_sizes[1] / 2;       // 640000
    const int nb = (nn + 255) / 256;

    const int smem1 = (2 * 128 * 136 + 2 * 128 * 136) * 2;   // 139264 B
    const int smem2 = (2 * 128 * 136 + 2 * 128 * 56) * 2;    //  98304 B
    cudaFuncSetAttribute(k_gemm_tc<1>, cudaFuncAttributeMaxDynamicSharedMemorySize, smem1);
    cudaFuncSetAttribute(k_gemm_tc<2>, cudaFuncAttributeMaxDynamicSharedMemorySize, smem2);

    k_probe<<<1, 256>>>(ei32);
    k_zero_deg<<<nb, 256>>>(nn);
    k_count<<<(ne + 255) / 256, 256>>>(ei32, ne, nn);
    k_scan1<<<nb, 256>>>(nn);
    k_scan2<<<1, 256>>>(nb);
    k_scan3<<<nb, 256>>>(nn, ne);
    k_fill<<<(ne + 255) / 256, 256>>>(ei32, ne, nn);
    k_splitW<<<(128 * 128 + 128 * 40 + 255) / 256, 256>>>(W1, W2);

    int gblk = (nn + 127) / 128;
    k_gemm_tc<1><<<gblk, 256, smem1>>>(x, nn);
    k_gather1<<<(nn + 7) / 8, 256>>>(b1, nn);
    k_gemm_tc<2><<<gblk, 256, smem2>>>(nullptr, nn);
    k_gather2<<<(nn + 7) / 8, 256>>>(out, b2, nn);
}

// round 13
// speedup vs baseline: 1.0030x; 1.0030x over previous
#include <cuda_runtime.h>
#include <cuda_bf16.h>
#include <stdint.h>

// GCN 2-layer, N=50000, E=640000, 128 -> 128(relu) -> 40.
// y = dinv*(x@W) via bf16x3 tensor-core GEMM; agg via CSR warp-gather; out = dinv*agg + b.

#define NN 50000
#define NE 640000

// ---- scratch (device globals; allocation forbidden) ----
__device__ int   g_is32;
__device__ int   g_eidx[NE];
__device__ int   g_rowptr[NN + 1];
__device__ int   g_cursor[NN];
__device__ int   g_rowtmp[NN];
__device__ int   g_bsum[256];
__device__ int   g_boff[256];
__device__ int   g_deg[NN];
__device__ float g_dinv[NN];
__device__ __align__(16) float g_y1[NN * 128];
__device__ __align__(16) float g_h [NN * 128];
__device__ __align__(16) float g_y2[NN * 40];
__device__ __align__(4) __nv_bfloat16 g_W1h[128 * 128], g_W1l[128 * 128];
__device__ __align__(4) __nv_bfloat16 g_W2h[128 * 40],  g_W2l[128 * 40];

// ---------------- prologue ----------------
__global__ void k_probe(const int* __restrict__ ei32) {
    int i = threadIdx.x;                      // odd 32-bit words 1..511
    if (i == 0) g_is32 = 0;
    __syncthreads();
    if (ei32[2 * i + 1] != 0) g_is32 = 1;     // int64 high halves all 0
}

__global__ void k_zero_deg(int nn) {
    int i = blockIdx.x * blockDim.x + threadIdx.x;
    if (i < nn) g_deg[i] = 0;
}

__global__ void k_count(const int* __restrict__ ei32, int ne, int nn) {
    int e = blockIdx.x * blockDim.x + threadIdx.x;
    if (e >= ne) return;
    int d = g_is32 ? ei32[ne + e] : ei32[2 * ne + 2 * e];
    d = ((unsigned)d < (unsigned)nn) ? d : 0;
    atomicAdd(&g_deg[d], 1);
}

__global__ void k_scan1(int nn) {
    __shared__ int s[256];
    int t = threadIdx.x;
    int i = blockIdx.x * 256 + t;
    int v = (i < nn) ? g_deg[i] : 0;
    s[t] = v;
    __syncthreads();
    for (int off = 1; off < 256; off <<= 1) {
        int add = (t >= off) ? s[t - off] : 0;
        __syncthreads();
        s[t] += add;
        __syncthreads();
    }
    if (i < nn) g_rowtmp[i] = s[t] - v;
    if (t == 255) g_bsum[blockIdx.x] = s[255];
}

__global__ void k_scan2(int nb) {
    __shared__ int s[256];
    int t = threadIdx.x;
    int v = (t < nb) ? g_bsum[t] : 0;
    s[t] = v;
    __syncthreads();
    for (int off = 1; off < 256; off <<= 1) {
        int add = (t >= off) ? s[t - off] : 0;
        __syncthreads();
        s[t] += add;
        __syncthreads();
    }
    g_boff[t] = s[t] - v;
}

__global__ void k_scan3(int nn, int ne) {
    int i = blockIdx.x * blockDim.x + threadIdx.x;
    if (i < nn) {
        int rp = g_rowtmp[i] + g_boff[i >> 8];
        g_rowptr[i] = rp;
        g_cursor[i] = rp;
        g_dinv[i] = rsqrtf((float)(g_deg[i] + 1));
    }
    if (i == 0) g_rowptr[nn] = ne;
}

__global__ void k_fill(const int* __restrict__ ei32, int ne, int nn) {
    int e = blockIdx.x * blockDim.x + threadIdx.x;
    if (e >= ne) return;
    int s, d;
    if (g_is32) { s = ei32[e];     d = ei32[ne + e]; }
    else        { s = ei32[2 * e]; d = ei32[2 * ne + 2 * e]; }
    s = ((unsigned)s < (unsigned)nn) ? s : 0;
    d = ((unsigned)d < (unsigned)nn) ? d : 0;
    int pos = atomicAdd(&g_cursor[d], 1);
    g_eidx[pos] = s;
}

// ---------------- weight split: W -> bf16 hi + bf16 lo ----------------
__global__ void k_splitW(const float* __restrict__ W1, const float* __restrict__ W2) {
    int i = blockIdx.x * blockDim.x + threadIdx.x;
    if (i < 128 * 128) {
        float v = W1[i];
        __nv_bfloat16 h = __float2bfloat16(v);
        g_W1h[i] = h;
        g_W1l[i] = __float2bfloat16(v - __bfloat162float(h));
    } else if (i < 128 * 128 + 128 * 40) {
        int j = i - 128 * 128;
        float v = W2[j];
        __nv_bfloat16 h = __float2bfloat16(v);
        g_W2h[j] = h;
        g_W2l[j] = __float2bfloat16(v - __bfloat162float(h));
    }
}

// ---------------- tensor-core GEMM (bf16x3) ----------------
__device__ __forceinline__ uint32_t s2u(const void* p) {
    return (uint32_t)__cvta_generic_to_shared(p);
}
__device__ __forceinline__ uint32_t pack2(float a, float b) {
    __nv_bfloat162 t = __floats2bfloat162_rn(a, b);
    return *(uint32_t*)&t;
}
__device__ __forceinline__ void ldsm_x4(uint32_t a[4], uint32_t addr) {
    asm volatile("ldmatrix.sync.aligned.m8n8.x4.shared.b16 {%0,%1,%2,%3},[%4];"
                 : "=r"(a[0]), "=r"(a[1]), "=r"(a[2]), "=r"(a[3]) : "r"(addr));
}
__device__ __forceinline__ void ldsm_x2t(uint32_t b[2], uint32_t addr) {
    asm volatile("ldmatrix.sync.aligned.m8n8.x2.trans.shared.b16 {%0,%1},[%2];"
                 : "=r"(b[0]), "=r"(b[1]) : "r"(addr));
}
__device__ __forceinline__ void mma16816(float d[4], const uint32_t a[4], const uint32_t b[2]) {
    asm volatile("mma.sync.aligned.m16n8k16.row.col.f32.bf16.bf16.f32 "
                 "{%0,%1,%2,%3},{%4,%5,%6,%7},{%8,%9},{%0,%1,%2,%3};"
                 : "+f"(d[0]), "+f"(d[1]), "+f"(d[2]), "+f"(d[3])
                 : "r"(a[0]), "r"(a[1]), "r"(a[2]), "r"(a[3]), "r"(b[0]), "r"(b[1]));
}

// LAYER 1: in = x (arg), W = g_W1h/l, out = g_y1, NW=128
// LAYER 2: in = g_h,     W = g_W2h/l, out = g_y2, NW=40
// Block: 256 threads (8 warps x m16), M-tile 128, full N.
template <int LAYER>
__global__ void k_gemm_tc(const float* __restrict__ xin, int nn) {
    constexpr int NW = (LAYER == 1) ? 128 : 40;
    constexpr int NT = NW / 8;                  // n-tiles
    constexpr int XP = 136;                     // padded x width (bf16)
    constexpr int WP = (LAYER == 1) ? 136 : 56; // padded w width (bank-safe)

    extern __shared__ __nv_bfloat16 sm[];
    __nv_bfloat16* xh = sm;
    __nv_bfloat16* xl = xh + 128 * XP;
    __nv_bfloat16* wh = xl + 128 * XP;
    __nv_bfloat16* wl = wh + 128 * WP;

    const float* in = (LAYER == 1) ? xin : (const float*)g_h;
    float* outp     = (LAYER == 1) ? g_y1 : g_y2;
    const __nv_bfloat16* Wh = (LAYER == 1) ? g_W1h : g_W2h;
    const __nv_bfloat16* Wl = (LAYER == 1) ? g_W1l : g_W2l;

    int tid = threadIdx.x;
    int m_base = blockIdx.x * 128;

    // load W (bf16 pre-split) into padded smem, pairwise
    const uint32_t* wsh = (const uint32_t*)Wh;
    const uint32_t* wsl = (const uint32_t*)Wl;
    for (int i = tid; i < 128 * NW / 2; i += 256) {
        int r = (2 * i) / NW, c = (2 * i) % NW;
        *(uint32_t*)&wh[r * WP + c] = wsh[i];
        *(uint32_t*)&wl[r * WP + c] = wsl[i];
    }
    // load + split x tile (128 x 128 fp32)
    for (int i = tid; i < 128 * 32; i += 256) {
        int r = i >> 5, cq = i & 31;
        int row = m_base + r;
        float4 v = make_float4(0.f, 0.f, 0.f, 0.f);
        if (row < nn) v = ((const float4*)(in + (size_t)row * 128))[cq];
        float hx = __bfloat162float(__float2bfloat16(v.x));
        float hy = __bfloat162float(__float2bfloat16(v.y));
        float hz = __bfloat162float(__float2bfloat16(v.z));
        float hw = __bfloat162float(__float2bfloat16(v.w));
        uint2 ph = make_uint2(pack2(v.x, v.y), pack2(v.z, v.w));
        uint2 pl = make_uint2(pack2(v.x - hx, v.y - hy), pack2(v.z - hz, v.w - hw));
        *(uint2*)&xh[r * XP + cq * 4] = ph;
        *(uint2*)&xl[r * XP + cq * 4] = pl;
    }
    __syncthreads();

    int warp = tid >> 5, lane = tid & 31;
    int mrow = warp * 16;

    float d[NT][4];
#pragma unroll
    for (int t = 0; t < NT; t++) { d[t][0] = d[t][1] = d[t][2] = d[t][3] = 0.f; }

    uint32_t xh_b = s2u(xh), xl_b = s2u(xl), wh_b = s2u(wh), wl_b = s2u(wl);
    uint32_t a_off = ((mrow + (lane & 15)) * XP + (lane >> 4) * 8) * 2;   // bytes
    uint32_t b_lrow = (lane & 15);

#pragma unroll
    for (int ks = 0; ks < 8; ks++) {
        uint32_t ah[4], al[4];
        ldsm_x4(ah, xh_b + a_off + ks * 32);
        ldsm_x4(al, xl_b + a_off + ks * 32);
        uint32_t brow = ((ks * 16 + b_lrow) * WP) * 2;
#pragma unroll
        for (int nt = 0; nt < NT; nt++) {
            uint32_t bh[2], bl[2];
            ldsm_x2t(bh, wh_b + brow + nt * 16);
            ldsm_x2t(bl, wl_b + brow + nt * 16);
            mma16816(d[nt], ah, bh);
            mma16816(d[nt], ah, bl);
            mma16816(d[nt], al, bh);
        }
    }

    int r0 = m_base + mrow + (lane >> 2);
    int r1 = r0 + 8;
    int c0 = (lane & 3) * 2;
    float di0 = (r0 < nn) ? g_dinv[r0] : 0.f;
    float di1 = (r1 < nn) ? g_dinv[r1] : 0.f;
#pragma unroll
    for (int nt = 0; nt < NT; nt++) {
        int col = nt * 8 + c0;
        if (r0 < nn) *(float2*)&outp[(size_t)r0 * NW + col] = make_float2(d[nt][0] * di0, d[nt][1] * di0);
        if (r1 < nn) *(float2*)&outp[(size_t)r1 * NW + col] = make_float2(d[nt][2] * di1, d[nt][3] * di1);
    }
}

// ---------------- layer 1 gather: h = relu(dinv*(y1[n] + sum y1[src]) + b1) ----------------
__global__ void k_gather1(const float* __restrict__ b1, int nn) {
    int warp = (blockIdx.x * blockDim.x + threadIdx.x) >> 5;
    if (warp >= nn) return;
    int q = threadIdx.x & 31;
    int n = warp;
    int beg = g_rowptr[n], end = g_rowptr[n + 1];
    float4 acc = ((const float4*)(g_y1 + (size_t)n * 128))[q];   // self loop
    int k = beg;
    for (; k + 3 < end; k += 4) {                                // 4 loads in flight
        int s0 = g_eidx[k], s1 = g_eidx[k + 1], s2 = g_eidx[k + 2], s3 = g_eidx[k + 3];
        float4 v0 = ((const float4*)(g_y1 + (size_t)s0 * 128))[q];
        float4 v1 = ((const float4*)(g_y1 + (size_t)s1 * 128))[q];
        float4 v2 = ((const float4*)(g_y1 + (size_t)s2 * 128))[q];
        float4 v3 = ((const float4*)(g_y1 + (size_t)s3 * 128))[q];
        acc.x += v0.x + v1.x + v2.x + v3.x;
        acc.y += v0.y + v1.y + v2.y + v3.y;
        acc.z += v0.z + v1.z + v2.z + v3.z;
        acc.w += v0.w + v1.w + v2.w + v3.w;
    }
    for (; k < end; k++) {
        int s = g_eidx[k];
        float4 v = ((const float4*)(g_y1 + (size_t)s * 128))[q];
        acc.x += v.x; acc.y += v.y; acc.z += v.z; acc.w += v.w;
    }
    float di = g_dinv[n];
    float4 b = ((const float4*)b1)[q];
    float4 h;
    h.x = fmaxf(fmaf(di, acc.x, b.x), 0.f);
    h.y = fmaxf(fmaf(di, acc.y, b.y), 0.f);
    h.z = fmaxf(fmaf(di, acc.z, b.z), 0.f);
    h.w = fmaxf(fmaf(di, acc.w, b.w), 0.f);
    ((float4*)(g_h + (size_t)n * 128))[q] = h;
}

// ---------------- layer 2 gather: out = dinv*(y2[n] + sum y2[src]) + b2 ----------------
__global__ void k_gather2(float* __restrict__ out, const float* __restrict__ b2, int nn) {
    int warp = (blockIdx.x * blockDim.x + threadIdx.x) >> 5;
    if (warp >= nn) return;
    int lane = threadIdx.x & 31;
    int n = warp;
    int beg = g_rowptr[n], end = g_rowptr[n + 1];
    int sub = lane / 10;                 // 0,1,2 active
    int q = lane % 10;
    float4 acc = make_float4(0.f, 0.f, 0.f, 0.f);
    if (sub == 0) acc = ((const float4*)(g_y2 + (size_t)n * 40))[q];   // self loop
    int k = (sub < 3) ? (beg + sub) : end;
    for (; k + 3 < end; k += 6) {        // 2 edges in flight per subgroup
        int s0 = g_eidx[k], s1 = g_eidx[k + 3];
        float4 v0 = *(const float4*)(g_y2 + (size_t)s0 * 40 + q * 4);
        float4 v1 = *(const float4*)(g_y2 + (size_t)s1 * 40 + q * 4);
        acc.x += v0.x + v1.x; acc.y += v0.y + v1.y;
        acc.z += v0.z + v1.z; acc.w += v0.w + v1.w;
    }
    if (k < end) {
        int s = g_eidx[k];
        float4 v = *(const float4*)(g_y2 + (size_t)s * 40 + q * 4);
        acc.x += v.x; acc.y += v.y; acc.z += v.z; acc.w += v.w;
    }
    unsigned m = 0xFFFFFFFFu;
    float ax = acc.x + __shfl_sync(m, acc.x, lane + 10) + __shfl_sync(m, acc.x, lane + 20);
    float ay = acc.y + __shfl_sync(m, acc.y, lane + 10) + __shfl_sync(m, acc.y, lane + 20);
    float az = acc.z + __shfl_sync(m, acc.z, lane + 10) + __shfl_sync(m, acc.z, lane + 20);
    float aw = acc.w + __shfl_sync(m, acc.w, lane + 10) + __shfl_sync(m, acc.w, lane + 20);
    if (lane < 10) {
        float di = g_dinv[n];
        float4 b = ((const float4*)b2)[q];
        float4 r;
        r.x = fmaf(di, ax, b.x);
        r.y = fmaf(di, ay, b.y);
        r.z = fmaf(di, az, b.z);
        r.w = fmaf(di, aw, b.w);
        ((float4*)(out + (size_t)n * 40))[q] = r;
    }
}

extern "C" void kernel_launch(void* const* d_in, const int* in_sizes, int n_in,
                              void* d_out, int out_size) {
    const float* x    = (const float*)d_in[0];
    const int*   ei32 = (const int*)d_in[1];
    const float* W1   = (const float*)d_in[2];
    const float* b1   = (const float*)d_in[3];
    const float* W2   = (const float*)d_in[4];
    const float* b2   = (const float*)d_in[5];
    float*       out  = (float*)d_out;

    const int nn = in_sizes[0] / 128;     // 50000
    const int ne = in_sizes[1] / 2;       // 640000
    const int nb = (nn + 255) / 256;

    const int smem1 = (2 * 128 * 136 + 2 * 128 * 136) * 2;   // 139264 B
    const int smem2 = (2 * 128 * 136 + 2 * 128 * 56) * 2;    //  98304 B
    cudaFuncSetAttribute(k_gemm_tc<1>, cudaFuncAttributeMaxDynamicSharedMemorySize, smem1);
    cudaFuncSetAttribute(k_gemm_tc<2>, cudaFuncAttributeMaxDynamicSharedMemorySize, smem2);

    k_probe<<<1, 256>>>(ei32);
    k_zero_deg<<<nb, 256>>>(nn);
    k_count<<<(ne + 255) / 256, 256>>>(ei32, ne, nn);
    k_scan1<<<nb, 256>>>(nn);
    k_scan2<<<1, 256>>>(nb);
    k_scan3<<<nb, 256>>>(nn, ne);
    k_fill<<<(ne + 255) / 256, 256>>>(ei32, ne, nn);
    k_splitW<<<(128 * 128 + 128 * 40 + 255) / 256, 256>>>(W1, W2);

    int gblk = (nn + 127) / 128;
    k_gemm_tc<1><<<gblk, 256, smem1>>>(x, nn);
    k_gather1<<<(nn + 7) / 8, 256>>>(b1, nn);
    k_gemm_tc<2><<<gblk, 256, smem2>>>(nullptr, nn);
    k_gather2<<<(nn + 7) / 8, 256>>>(out, b2, nn);
}